// round 2
// baseline (speedup 1.0000x reference)
#include <cuda_runtime.h>
#include <math.h>

// Problem constants
#define BSZ   4
#define NLEN  4096
#define DIM_  1024
#define HEADS 16
#define HD    64
#define FEAT  256
#define ROWS  (BSZ * NLEN)   // 16384
#define GSPLIT 8

// ---------------- scratch (__device__ globals; no allocation allowed) ------
__device__ float g_q[(size_t)ROWS * DIM_];                       // elu(q)+1
__device__ float g_k[(size_t)ROWS * DIM_];                       // elu(k)+1
__device__ float g_v[(size_t)ROWS * DIM_];                       // v
__device__ float g_Gpart[(size_t)GSPLIT * BSZ * HEADS * HD * HD];
__device__ float g_P[HD * HD];                                   // RF @ RF^T
__device__ float g_M[(size_t)BSZ * HEADS * HD * HD];             // P @ G
__device__ float g_W2[(size_t)BSZ * DIM_ * DIM_];                // blockdiag(M) @ Wo

__device__ __forceinline__ float act_elu1(float x) {
    // elu(x)+1 : x>0 ? x+1 : exp(x)
    return x > 0.f ? x + 1.f : expf(x);
}

// ---------------- SGEMM: C = A(MxK) @ B(KxN) + bias, optional elu+1 --------
// BM=128, BN=128, BK=8, 256 threads, 8x8 per-thread microtile.
template <int ACT>
__global__ __launch_bounds__(256) void sgemm_bias_act(
    const float* __restrict__ A, const float* __restrict__ Bm,
    const float* __restrict__ bias, float* __restrict__ C,
    int M, int N, int K, long sA, long sB, long sC)
{
    __shared__ float As[8][128];
    __shared__ float Bs[8][128];

    long bz = blockIdx.z;
    A  += bz * sA;
    Bm += bz * sB;
    C  += bz * sC;

    const int tid  = threadIdx.x;
    const int brow = blockIdx.y * 128;
    const int bcol = blockIdx.x * 128;

    const int tr = (tid / 16) * 8;   // row of microtile within block tile
    const int tc = (tid % 16) * 8;   // col

    const int arow = tid >> 1;            // 0..127
    const int acol = (tid & 1) * 4;       // 0 or 4
    const int brw  = tid >> 5;            // 0..7
    const int bcl  = (tid & 31) * 4;      // 0..124

    const float* Aptr = A + (long)(brow + arow) * K + acol;
    const float* Bptr = Bm + (long)brw * N + bcol + bcl;

    float acc[8][8];
#pragma unroll
    for (int i = 0; i < 8; i++)
#pragma unroll
        for (int j = 0; j < 8; j++) acc[i][j] = 0.f;

    for (int k0 = 0; k0 < K; k0 += 8) {
        float4 av = *(const float4*)(Aptr + k0);
        float4 bv = *(const float4*)(Bptr + (long)k0 * N);
        As[acol + 0][arow] = av.x;
        As[acol + 1][arow] = av.y;
        As[acol + 2][arow] = av.z;
        As[acol + 3][arow] = av.w;
        *(float4*)&Bs[brw][bcl] = bv;
        __syncthreads();

#pragma unroll
        for (int kk = 0; kk < 8; kk++) {
            float ar[8], br[8];
#pragma unroll
            for (int i = 0; i < 8; i++) ar[i] = As[kk][tr + i];
#pragma unroll
            for (int j = 0; j < 8; j++) br[j] = Bs[kk][tc + j];
#pragma unroll
            for (int i = 0; i < 8; i++)
#pragma unroll
                for (int j = 0; j < 8; j++)
                    acc[i][j] = fmaf(ar[i], br[j], acc[i][j]);
        }
        __syncthreads();
    }

    // epilogue: bias + optional activation, vectorized stores
#pragma unroll
    for (int i = 0; i < 8; i++) {
        long crow = brow + tr + i;
#pragma unroll
        for (int j = 0; j < 8; j += 4) {
            int col = bcol + tc + j;
            float4 o;
            o.x = acc[i][j + 0] + bias[col + 0];
            o.y = acc[i][j + 1] + bias[col + 1];
            o.z = acc[i][j + 2] + bias[col + 2];
            o.w = acc[i][j + 3] + bias[col + 3];
            if (ACT == 1) {
                o.x = act_elu1(o.x);
                o.y = act_elu1(o.y);
                o.z = act_elu1(o.z);
                o.w = act_elu1(o.w);
            }
            *(float4*)(C + crow * N + col) = o;
        }
    }
}

// ---------------- P = RF @ RF^T (64x64) ------------------------------------
__global__ __launch_bounds__(256) void pmat_kernel(const float* __restrict__ RF,
                                                   float* __restrict__ P)
{
    __shared__ float RFs[64][65];   // one 64-wide F slab at a time
    const int tid = threadIdx.x;
    const int i  = tid / 4;          // output row e
    const int j0 = (tid % 4) * 16;   // output col start
    float acc[16];
#pragma unroll
    for (int j = 0; j < 16; j++) acc[j] = 0.f;

    for (int f0 = 0; f0 < FEAT; f0 += 64) {
        // load RF[:, f0:f0+64]: 64x64 floats, coalesced
        for (int t = tid; t < 64 * 16; t += 256) {
            int r = t / 16, c4 = (t % 16) * 4;
            float4 v = *(const float4*)(RF + (long)r * FEAT + f0 + c4);
            RFs[r][c4 + 0] = v.x;
            RFs[r][c4 + 1] = v.y;
            RFs[r][c4 + 2] = v.z;
            RFs[r][c4 + 3] = v.w;
        }
        __syncthreads();
#pragma unroll 8
        for (int f = 0; f < 64; f++) {
            float a = RFs[i][f];
#pragma unroll
            for (int j = 0; j < 16; j++)
                acc[j] = fmaf(a, RFs[j0 + j][f], acc[j]);
        }
        __syncthreads();
    }
#pragma unroll
    for (int j = 0; j < 16; j++) P[i * HD + j0 + j] = acc[j];
}

// ---------------- G partials: G(b,h) += k1[chunk]^T @ v[chunk] --------------
// grid: (B*H, GSPLIT); 256 threads; 4x4 per-thread microtile of 64x64 output.
__global__ __launch_bounds__(256) void kv_outer_kernel(const float* __restrict__ Kmat,
                                                       const float* __restrict__ Vmat,
                                                       float* __restrict__ Gp)
{
    const int bh = blockIdx.x;
    const int b = bh / HEADS, h = bh % HEADS;
    const int split = blockIdx.y;
    const int n0 = split * (NLEN / GSPLIT);
    const int CH = 32;

    __shared__ float Ks[CH][HD];
    __shared__ float Vs[CH][HD];

    const int tid = threadIdx.x;
    const int ty = tid / 16, tx = tid % 16;
    float acc[4][4];
#pragma unroll
    for (int i = 0; i < 4; i++)
#pragma unroll
        for (int j = 0; j < 4; j++) acc[i][j] = 0.f;

    const long base = ((long)b * NLEN) * DIM_ + h * HD;

    for (int n = n0; n < n0 + NLEN / GSPLIT; n += CH) {
        for (int t = tid; t < CH * 16; t += 256) {   // 512 float4 loads, 2 per thread
            int r = t / 16, c4 = (t % 16) * 4;
            *(float4*)&Ks[r][c4] = *(const float4*)(Kmat + base + (long)(n + r) * DIM_ + c4);
            *(float4*)&Vs[r][c4] = *(const float4*)(Vmat + base + (long)(n + r) * DIM_ + c4);
        }
        __syncthreads();
#pragma unroll
        for (int kk = 0; kk < CH; kk++) {
            float kr[4], vr[4];
#pragma unroll
            for (int i = 0; i < 4; i++) kr[i] = Ks[kk][ty * 4 + i];
#pragma unroll
            for (int j = 0; j < 4; j++) vr[j] = Vs[kk][tx * 4 + j];
#pragma unroll
            for (int i = 0; i < 4; i++)
#pragma unroll
                for (int j = 0; j < 4; j++)
                    acc[i][j] = fmaf(kr[i], vr[j], acc[i][j]);
        }
        __syncthreads();
    }

    float* out = Gp + ((long)split * BSZ * HEADS + bh) * HD * HD;
#pragma unroll
    for (int i = 0; i < 4; i++)
#pragma unroll
        for (int j = 0; j < 4; j++)
            out[(ty * 4 + i) * HD + tx * 4 + j] = acc[i][j];
}

// ---------------- reduce G partials, M = P @ G ------------------------------
__global__ __launch_bounds__(256) void gm_kernel(const float* __restrict__ Gp,
                                                 const float* __restrict__ P,
                                                 float* __restrict__ Mout)
{
    const int bh = blockIdx.x;
    __shared__ float Gs[HD][HD];
    __shared__ float Ps[HD][HD];
    const int tid = threadIdx.x;

    for (int t = tid; t < HD * HD; t += 256) {
        float s = 0.f;
#pragma unroll
        for (int sp = 0; sp < GSPLIT; sp++)
            s += Gp[((long)sp * BSZ * HEADS + bh) * HD * HD + t];
        Gs[t / HD][t % HD] = s;
        Ps[t / HD][t % HD] = P[t];
    }
    __syncthreads();

    const int e = tid / 4;
    const int d0 = (tid % 4) * 16;
    float acc[16];
#pragma unroll
    for (int j = 0; j < 16; j++) acc[j] = 0.f;
#pragma unroll 8
    for (int c = 0; c < HD; c++) {
        float pe = Ps[e][c];
#pragma unroll
        for (int j = 0; j < 16; j++)
            acc[j] = fmaf(pe, Gs[c][d0 + j], acc[j]);
    }
#pragma unroll
    for (int j = 0; j < 16; j++)
        Mout[(long)bh * HD * HD + e * HD + d0 + j] = acc[j];
}

// ---------------- W2(b)[(h,e),c] = sum_d M(b,h)[e,d] * Wo[h*64+d, c] --------
// grid: (B*H, DIM/128); 256 threads.
__global__ __launch_bounds__(256) void w2_kernel(const float* __restrict__ Mmat,
                                                 const float* __restrict__ Wo,
                                                 float* __restrict__ W2)
{
    const int bh = blockIdx.x;
    const int b = bh / HEADS, h = bh % HEADS;
    const int c0 = blockIdx.y * 128;

    __shared__ float Ms[HD][HD];
    const int tid = threadIdx.x;
    for (int t = tid; t < HD * HD; t += 256)
        Ms[t / HD][t % HD] = Mmat[(long)bh * HD * HD + t];
    __syncthreads();

    const int col = c0 + (tid & 127);
    const int e0  = (tid >> 7) * 32;
    float acc[32];
#pragma unroll
    for (int e = 0; e < 32; e++) acc[e] = 0.f;
#pragma unroll 4
    for (int d = 0; d < HD; d++) {
        float w = Wo[(long)(h * HD + d) * DIM_ + col];
#pragma unroll
        for (int e = 0; e < 32; e++)
            acc[e] = fmaf(Ms[e0 + e][d], w, acc[e]);
    }
#pragma unroll
    for (int e = 0; e < 32; e++)
        W2[(long)b * DIM_ * DIM_ + (long)(h * HD + e0 + e) * DIM_ + col] = acc[e];
}

// ---------------- launch ----------------------------------------------------
extern "C" void kernel_launch(void* const* d_in, const int* in_sizes, int n_in,
                              void* d_out, int out_size)
{
    const float* x   = (const float*)d_in[0];
    const float* Wq  = (const float*)d_in[1];
    const float* bq  = (const float*)d_in[2];
    const float* Wk  = (const float*)d_in[3];
    const float* bk  = (const float*)d_in[4];
    const float* Wv  = (const float*)d_in[5];
    const float* bv  = (const float*)d_in[6];
    const float* Wo  = (const float*)d_in[7];
    const float* bo  = (const float*)d_in[8];
    const float* RF  = (const float*)d_in[9];
    float* out = (float*)d_out;

    float *qp, *kp, *vp, *gpp, *pp, *mp, *w2p;
    cudaGetSymbolAddress((void**)&qp,  g_q);
    cudaGetSymbolAddress((void**)&kp,  g_k);
    cudaGetSymbolAddress((void**)&vp,  g_v);
    cudaGetSymbolAddress((void**)&gpp, g_Gpart);
    cudaGetSymbolAddress((void**)&pp,  g_P);
    cudaGetSymbolAddress((void**)&mp,  g_M);
    cudaGetSymbolAddress((void**)&w2p, g_W2);

    // 1) QKV projections (+elu+1 on q,k)
    dim3 g1(DIM_ / 128, ROWS / 128, 1);
    sgemm_bias_act<1><<<g1, 256>>>(x, Wq, bq, qp, ROWS, DIM_, DIM_, 0, 0, 0);
    sgemm_bias_act<1><<<g1, 256>>>(x, Wk, bk, kp, ROWS, DIM_, DIM_, 0, 0, 0);
    sgemm_bias_act<0><<<g1, 256>>>(x, Wv, bv, vp, ROWS, DIM_, DIM_, 0, 0, 0);

    // 2) P = RF @ RF^T
    pmat_kernel<<<1, 256>>>(RF, pp);

    // 3) G partials: k1^T v per (b,h), split over N
    kv_outer_kernel<<<dim3(BSZ * HEADS, GSPLIT), 256>>>(kp, vp, gpp);

    // 4) reduce + M = P @ G
    gm_kernel<<<BSZ * HEADS, 256>>>(gpp, pp, mp);

    // 5) W2(b) = blockdiag(M) @ Wo
    w2_kernel<<<dim3(BSZ * HEADS, DIM_ / 128), 256>>>(mp, Wo, w2p);

    // 6) final: out(b) = q1(b) @ W2(b) + bo  (batched)
    dim3 g2(DIM_ / 128, NLEN / 128, BSZ);
    sgemm_bias_act<0><<<g2, 256>>>(qp, w2p, bo, out,
                                   NLEN, DIM_, DIM_,
                                   (long)NLEN * DIM_, (long)DIM_ * DIM_, (long)NLEN * DIM_);
}

// round 3
// speedup vs baseline: 1.0012x; 1.0012x over previous
#include <cuda_runtime.h>
#include <math.h>

// Problem constants
#define BSZ   4
#define NLEN  4096
#define DIM_  1024
#define HEADS 16
#define HD    64
#define FEAT  256
#define ROWS  (BSZ * NLEN)   // 16384
#define GSPLIT 8

// ---------------- scratch (__device__ globals; no allocation allowed) ------
__device__ float g_q[(size_t)ROWS * DIM_];                       // elu(q)+1
__device__ float g_k[(size_t)ROWS * DIM_];                       // elu(k)+1
__device__ float g_v[(size_t)ROWS * DIM_];                       // v
__device__ float g_Gpart[(size_t)GSPLIT * BSZ * HEADS * HD * HD];
__device__ float g_P[HD * HD];                                   // RF @ RF^T
__device__ float g_M[(size_t)BSZ * HEADS * HD * HD];             // P @ G
__device__ float g_W2[(size_t)BSZ * DIM_ * DIM_];                // blockdiag(M) @ Wo

__device__ __forceinline__ float act_elu1(float x) {
    // elu(x)+1 : x>0 ? x+1 : exp(x)
    return x > 0.f ? x + 1.f : expf(x);
}

// ---------------- SGEMM: C = A(MxK) @ B(KxN) + bias, optional elu+1 --------
// BM=128, BN=128, BK=8, 256 threads, 8x8 per-thread microtile.
template <int ACT>
__global__ __launch_bounds__(256) void sgemm_bias_act(
    const float* __restrict__ A, const float* __restrict__ Bm,
    const float* __restrict__ bias, float* __restrict__ C,
    int M, int N, int K, long sA, long sB, long sC)
{
    __shared__ float As[8][128];
    __shared__ float Bs[8][128];

    long bz = blockIdx.z;
    A  += bz * sA;
    Bm += bz * sB;
    C  += bz * sC;

    const int tid  = threadIdx.x;
    const int brow = blockIdx.y * 128;
    const int bcol = blockIdx.x * 128;

    const int tr = (tid / 16) * 8;   // row of microtile within block tile
    const int tc = (tid % 16) * 8;   // col

    const int arow = tid >> 1;            // 0..127
    const int acol = (tid & 1) * 4;       // 0 or 4
    const int brw  = tid >> 5;            // 0..7
    const int bcl  = (tid & 31) * 4;      // 0..124

    const float* Aptr = A + (long)(brow + arow) * K + acol;
    const float* Bptr = Bm + (long)brw * N + bcol + bcl;

    float acc[8][8];
#pragma unroll
    for (int i = 0; i < 8; i++)
#pragma unroll
        for (int j = 0; j < 8; j++) acc[i][j] = 0.f;

    for (int k0 = 0; k0 < K; k0 += 8) {
        float4 av = *(const float4*)(Aptr + k0);
        float4 bv = *(const float4*)(Bptr + (long)k0 * N);
        As[acol + 0][arow] = av.x;
        As[acol + 1][arow] = av.y;
        As[acol + 2][arow] = av.z;
        As[acol + 3][arow] = av.w;
        *(float4*)&Bs[brw][bcl] = bv;
        __syncthreads();

#pragma unroll
        for (int kk = 0; kk < 8; kk++) {
            float ar[8], br[8];
#pragma unroll
            for (int i = 0; i < 8; i++) ar[i] = As[kk][tr + i];
#pragma unroll
            for (int j = 0; j < 8; j++) br[j] = Bs[kk][tc + j];
#pragma unroll
            for (int i = 0; i < 8; i++)
#pragma unroll
                for (int j = 0; j < 8; j++)
                    acc[i][j] = fmaf(ar[i], br[j], acc[i][j]);
        }
        __syncthreads();
    }

    // epilogue: bias + optional activation, vectorized stores
#pragma unroll
    for (int i = 0; i < 8; i++) {
        long crow = brow + tr + i;
#pragma unroll
        for (int j = 0; j < 8; j += 4) {
            int col = bcol + tc + j;
            float4 o;
            o.x = acc[i][j + 0] + bias[col + 0];
            o.y = acc[i][j + 1] + bias[col + 1];
            o.z = acc[i][j + 2] + bias[col + 2];
            o.w = acc[i][j + 3] + bias[col + 3];
            if (ACT == 1) {
                o.x = act_elu1(o.x);
                o.y = act_elu1(o.y);
                o.z = act_elu1(o.z);
                o.w = act_elu1(o.w);
            }
            *(float4*)(C + crow * N + col) = o;
        }
    }
}

// ---------------- P = RF @ RF^T (64x64) ------------------------------------
__global__ __launch_bounds__(256) void pmat_kernel(const float* __restrict__ RF,
                                                   float* __restrict__ P)
{
    __shared__ float RFs[64][65];   // one 64-wide F slab at a time
    const int tid = threadIdx.x;
    const int i  = tid / 4;          // output row e
    const int j0 = (tid % 4) * 16;   // output col start
    float acc[16];
#pragma unroll
    for (int j = 0; j < 16; j++) acc[j] = 0.f;

    for (int f0 = 0; f0 < FEAT; f0 += 64) {
        // load RF[:, f0:f0+64]: 64x64 floats, coalesced
        for (int t = tid; t < 64 * 16; t += 256) {
            int r = t / 16, c4 = (t % 16) * 4;
            float4 v = *(const float4*)(RF + (long)r * FEAT + f0 + c4);
            RFs[r][c4 + 0] = v.x;
            RFs[r][c4 + 1] = v.y;
            RFs[r][c4 + 2] = v.z;
            RFs[r][c4 + 3] = v.w;
        }
        __syncthreads();
#pragma unroll 8
        for (int f = 0; f < 64; f++) {
            float a = RFs[i][f];
#pragma unroll
            for (int j = 0; j < 16; j++)
                acc[j] = fmaf(a, RFs[j0 + j][f], acc[j]);
        }
        __syncthreads();
    }
#pragma unroll
    for (int j = 0; j < 16; j++) P[i * HD + j0 + j] = acc[j];
}

// ---------------- G partials: G(b,h) += k1[chunk]^T @ v[chunk] --------------
// grid: (B*H, GSPLIT); 256 threads; 4x4 per-thread microtile of 64x64 output.
__global__ __launch_bounds__(256) void kv_outer_kernel(const float* __restrict__ Kmat,
                                                       const float* __restrict__ Vmat,
                                                       float* __restrict__ Gp)
{
    const int bh = blockIdx.x;
    const int b = bh / HEADS, h = bh % HEADS;
    const int split = blockIdx.y;
    const int n0 = split * (NLEN / GSPLIT);
    const int CH = 32;

    __shared__ float Ks[CH][HD];
    __shared__ float Vs[CH][HD];

    const int tid = threadIdx.x;
    const int ty = tid / 16, tx = tid % 16;
    float acc[4][4];
#pragma unroll
    for (int i = 0; i < 4; i++)
#pragma unroll
        for (int j = 0; j < 4; j++) acc[i][j] = 0.f;

    const long base = ((long)b * NLEN) * DIM_ + h * HD;

    for (int n = n0; n < n0 + NLEN / GSPLIT; n += CH) {
        for (int t = tid; t < CH * 16; t += 256) {   // 512 float4 loads, 2 per thread
            int r = t / 16, c4 = (t % 16) * 4;
            *(float4*)&Ks[r][c4] = *(const float4*)(Kmat + base + (long)(n + r) * DIM_ + c4);
            *(float4*)&Vs[r][c4] = *(const float4*)(Vmat + base + (long)(n + r) * DIM_ + c4);
        }
        __syncthreads();
#pragma unroll
        for (int kk = 0; kk < CH; kk++) {
            float kr[4], vr[4];
#pragma unroll
            for (int i = 0; i < 4; i++) kr[i] = Ks[kk][ty * 4 + i];
#pragma unroll
            for (int j = 0; j < 4; j++) vr[j] = Vs[kk][tx * 4 + j];
#pragma unroll
            for (int i = 0; i < 4; i++)
#pragma unroll
                for (int j = 0; j < 4; j++)
                    acc[i][j] = fmaf(kr[i], vr[j], acc[i][j]);
        }
        __syncthreads();
    }

    float* out = Gp + ((long)split * BSZ * HEADS + bh) * HD * HD;
#pragma unroll
    for (int i = 0; i < 4; i++)
#pragma unroll
        for (int j = 0; j < 4; j++)
            out[(ty * 4 + i) * HD + tx * 4 + j] = acc[i][j];
}

// ---------------- reduce G partials, M = P @ G ------------------------------
__global__ __launch_bounds__(256) void gm_kernel(const float* __restrict__ Gp,
                                                 const float* __restrict__ P,
                                                 float* __restrict__ Mout)
{
    const int bh = blockIdx.x;
    __shared__ float Gs[HD][HD];
    __shared__ float Ps[HD][HD];
    const int tid = threadIdx.x;

    for (int t = tid; t < HD * HD; t += 256) {
        float s = 0.f;
#pragma unroll
        for (int sp = 0; sp < GSPLIT; sp++)
            s += Gp[((long)sp * BSZ * HEADS + bh) * HD * HD + t];
        Gs[t / HD][t % HD] = s;
        Ps[t / HD][t % HD] = P[t];
    }
    __syncthreads();

    const int e = tid / 4;
    const int d0 = (tid % 4) * 16;
    float acc[16];
#pragma unroll
    for (int j = 0; j < 16; j++) acc[j] = 0.f;
#pragma unroll 8
    for (int c = 0; c < HD; c++) {
        float pe = Ps[e][c];
#pragma unroll
        for (int j = 0; j < 16; j++)
            acc[j] = fmaf(pe, Gs[c][d0 + j], acc[j]);
    }
#pragma unroll
    for (int j = 0; j < 16; j++)
        Mout[(long)bh * HD * HD + e * HD + d0 + j] = acc[j];
}

// ---------------- W2(b)[(h,e),c] = sum_d M(b,h)[e,d] * Wo[h*64+d, c] --------
// grid: (B*H, DIM/128); 256 threads.
__global__ __launch_bounds__(256) void w2_kernel(const float* __restrict__ Mmat,
                                                 const float* __restrict__ Wo,
                                                 float* __restrict__ W2)
{
    const int bh = blockIdx.x;
    const int b = bh / HEADS, h = bh % HEADS;
    const int c0 = blockIdx.y * 128;

    __shared__ float Ms[HD][HD];
    const int tid = threadIdx.x;
    for (int t = tid; t < HD * HD; t += 256)
        Ms[t / HD][t % HD] = Mmat[(long)bh * HD * HD + t];
    __syncthreads();

    const int col = c0 + (tid & 127);
    const int e0  = (tid >> 7) * 32;
    float acc[32];
#pragma unroll
    for (int e = 0; e < 32; e++) acc[e] = 0.f;
#pragma unroll 4
    for (int d = 0; d < HD; d++) {
        float w = Wo[(long)(h * HD + d) * DIM_ + col];
#pragma unroll
        for (int e = 0; e < 32; e++)
            acc[e] = fmaf(Ms[e0 + e][d], w, acc[e]);
    }
#pragma unroll
    for (int e = 0; e < 32; e++)
        W2[(long)b * DIM_ * DIM_ + (long)(h * HD + e0 + e) * DIM_ + col] = acc[e];
}

// ---------------- launch ----------------------------------------------------
extern "C" void kernel_launch(void* const* d_in, const int* in_sizes, int n_in,
                              void* d_out, int out_size)
{
    const float* x   = (const float*)d_in[0];
    const float* Wq  = (const float*)d_in[1];
    const float* bq  = (const float*)d_in[2];
    const float* Wk  = (const float*)d_in[3];
    const float* bk  = (const float*)d_in[4];
    const float* Wv  = (const float*)d_in[5];
    const float* bv  = (const float*)d_in[6];
    const float* Wo  = (const float*)d_in[7];
    const float* bo  = (const float*)d_in[8];
    const float* RF  = (const float*)d_in[9];
    float* out = (float*)d_out;

    float *qp, *kp, *vp, *gpp, *pp, *mp, *w2p;
    cudaGetSymbolAddress((void**)&qp,  g_q);
    cudaGetSymbolAddress((void**)&kp,  g_k);
    cudaGetSymbolAddress((void**)&vp,  g_v);
    cudaGetSymbolAddress((void**)&gpp, g_Gpart);
    cudaGetSymbolAddress((void**)&pp,  g_P);
    cudaGetSymbolAddress((void**)&mp,  g_M);
    cudaGetSymbolAddress((void**)&w2p, g_W2);

    // 1) QKV projections (+elu+1 on q,k)
    dim3 g1(DIM_ / 128, ROWS / 128, 1);
    sgemm_bias_act<1><<<g1, 256>>>(x, Wq, bq, qp, ROWS, DIM_, DIM_, 0, 0, 0);
    sgemm_bias_act<1><<<g1, 256>>>(x, Wk, bk, kp, ROWS, DIM_, DIM_, 0, 0, 0);
    sgemm_bias_act<0><<<g1, 256>>>(x, Wv, bv, vp, ROWS, DIM_, DIM_, 0, 0, 0);

    // 2) P = RF @ RF^T
    pmat_kernel<<<1, 256>>>(RF, pp);

    // 3) G partials: k1^T v per (b,h), split over N
    kv_outer_kernel<<<dim3(BSZ * HEADS, GSPLIT), 256>>>(kp, vp, gpp);

    // 4) reduce + M = P @ G
    gm_kernel<<<BSZ * HEADS, 256>>>(gpp, pp, mp);

    // 5) W2(b) = blockdiag(M) @ Wo
    w2_kernel<<<dim3(BSZ * HEADS, DIM_ / 128), 256>>>(mp, Wo, w2p);

    // 6) final: out(b) = q1(b) @ W2(b) + bo  (batched)
    dim3 g2(DIM_ / 128, NLEN / 128, BSZ);
    sgemm_bias_act<0><<<g2, 256>>>(qp, w2p, bo, out,
                                   NLEN, DIM_, DIM_,
                                   (long)NLEN * DIM_, (long)DIM_ * DIM_, (long)NLEN * DIM_);
}

// round 5
// speedup vs baseline: 1.8917x; 1.8894x over previous
#include <cuda_runtime.h>
#include <cuda_bf16.h>
#include <cstdint>
#include <math.h>

// Problem constants
#define BSZ   4
#define NLEN  4096
#define DIM_  1024
#define HEADS 16
#define HD    64
#define FEAT  256
#define ROWS  (BSZ * NLEN)   // 16384
#define GSPLIT 8

// ---------------- scratch (__device__ globals; no allocation allowed) ------
__device__ __align__(16) __nv_bfloat16 g_xh[(size_t)ROWS * DIM_];
__device__ __align__(16) __nv_bfloat16 g_xl[(size_t)ROWS * DIM_];
__device__ __align__(16) __nv_bfloat16 g_q1h[(size_t)ROWS * DIM_];
__device__ __align__(16) __nv_bfloat16 g_q1l[(size_t)ROWS * DIM_];
__device__ __align__(16) float g_k[(size_t)ROWS * DIM_];
__device__ __align__(16) float g_v[(size_t)ROWS * DIM_];
__device__ __align__(16) __nv_bfloat16 g_wth[3][(size_t)DIM_ * DIM_];   // W^T hi
__device__ __align__(16) __nv_bfloat16 g_wtl[3][(size_t)DIM_ * DIM_];   // W^T lo
__device__ __align__(16) __nv_bfloat16 g_w2th[(size_t)BSZ * DIM_ * DIM_];
__device__ __align__(16) __nv_bfloat16 g_w2tl[(size_t)BSZ * DIM_ * DIM_];
__device__ float g_Gpart[(size_t)GSPLIT * BSZ * HEADS * HD * HD];
__device__ float g_P[HD * HD];
__device__ float g_M[(size_t)BSZ * HEADS * HD * HD];

__device__ __forceinline__ float act_elu1(float x) {
    return x > 0.f ? x + 1.f : expf(x);
}

// ======================= PTX helpers (non-'a' ISA only) =====================
__device__ __forceinline__ uint32_t smem_u32(const void* p) {
    return (uint32_t)__cvta_generic_to_shared(p);
}

__device__ __forceinline__ void cp16(uint32_t smem, const void* g) {
    asm volatile("cp.async.cg.shared.global [%0], [%1], 16;\n" :: "r"(smem), "l"(g));
}
__device__ __forceinline__ void cp_commit() {
    asm volatile("cp.async.commit_group;\n" ::: "memory");
}
template <int N>
__device__ __forceinline__ void cp_wait() {
    asm volatile("cp.async.wait_group %0;\n" :: "n"(N) : "memory");
}

__device__ __forceinline__ void ldm_x4(uint32_t* r, uint32_t addr) {
    asm volatile("ldmatrix.sync.aligned.m8n8.x4.shared.b16 {%0,%1,%2,%3}, [%4];"
                 : "=r"(r[0]), "=r"(r[1]), "=r"(r[2]), "=r"(r[3]) : "r"(addr));
}

__device__ __forceinline__ void mma_bf16(float* c, const uint32_t* a, uint32_t b0, uint32_t b1) {
    asm volatile(
        "mma.sync.aligned.m16n8k16.row.col.f32.bf16.bf16.f32 "
        "{%0,%1,%2,%3}, {%4,%5,%6,%7}, {%8,%9}, {%0,%1,%2,%3};"
        : "+f"(c[0]), "+f"(c[1]), "+f"(c[2]), "+f"(c[3])
        : "r"(a[0]), "r"(a[1]), "r"(a[2]), "r"(a[3]), "r"(b0), "r"(b1));
}

__device__ __forceinline__ uint32_t bfpack(float a, float b) {
    __nv_bfloat16 h0 = __float2bfloat16(a), h1 = __float2bfloat16(b);
    return (uint32_t)__bfloat16_as_ushort(h0) | ((uint32_t)__bfloat16_as_ushort(h1) << 16);
}

// ======================= conversion kernels ================================
__global__ __launch_bounds__(256) void conv_x_kernel(const float4* __restrict__ x,
                                                     uint2* __restrict__ xh,
                                                     uint2* __restrict__ xl, int n4)
{
    int i = blockIdx.x * 256 + threadIdx.x;
    if (i >= n4) return;
    float4 v = x[i];
    __nv_bfloat16 h0 = __float2bfloat16(v.x), h1 = __float2bfloat16(v.y);
    __nv_bfloat16 h2 = __float2bfloat16(v.z), h3 = __float2bfloat16(v.w);
    uint2 H, L;
    H.x = (uint32_t)__bfloat16_as_ushort(h0) | ((uint32_t)__bfloat16_as_ushort(h1) << 16);
    H.y = (uint32_t)__bfloat16_as_ushort(h2) | ((uint32_t)__bfloat16_as_ushort(h3) << 16);
    L.x = bfpack(v.x - __bfloat162float(h0), v.y - __bfloat162float(h1));
    L.y = bfpack(v.z - __bfloat162float(h2), v.w - __bfloat162float(h3));
    xh[i] = H;
    xl[i] = L;
}

// transpose + split: Wt[n,k] = W[k,n]
__global__ __launch_bounds__(1024) void conv_w_kernel(const float* __restrict__ W,
                                                      __nv_bfloat16* __restrict__ Wth,
                                                      __nv_bfloat16* __restrict__ Wtl)
{
    __shared__ float t[32][33];
    int tx = threadIdx.x, ty = threadIdx.y;
    int k = blockIdx.y * 32 + ty, n = blockIdx.x * 32 + tx;
    t[ty][tx] = W[(long)k * DIM_ + n];
    __syncthreads();
    float v = t[tx][ty];
    long o = (long)(blockIdx.x * 32 + ty) * DIM_ + blockIdx.y * 32 + tx;
    __nv_bfloat16 h = __float2bfloat16(v);
    Wth[o] = h;
    Wtl[o] = __float2bfloat16(v - __bfloat162float(h));
}

// ======================= mma.sync bf16x3 GEMM ===============================
// C(M x N) = A(M x K) @ Bt(N x K)^T + bias.  A/B in bf16 hi/lo pairs, K-major.
// Block tile 128x128, BK=32, 8 warps (warp tile 64x32), 3-stage cp.async.
#define BK 32
#define RSTRIDE 80                       // 64B row + 16B pad (conflict-free ldmatrix)
#define SA_H 0
#define SA_L (128 * RSTRIDE)
#define SB_H (2 * 128 * RSTRIDE)
#define SB_L (3 * 128 * RSTRIDE)
#define STAGE_BYTES (4 * 128 * RSTRIDE)  // 40960
#define NSTAGES 3
#define GEMM_SMEM (NSTAGES * STAGE_BYTES)

template <int ACT, int OUTBF>
__global__ __launch_bounds__(256) void gemm_tc(
    const __nv_bfloat16* __restrict__ Ah, const __nv_bfloat16* __restrict__ Al,
    const __nv_bfloat16* __restrict__ Bh, const __nv_bfloat16* __restrict__ Bl,
    const float* __restrict__ bias,
    float* __restrict__ Cf, __nv_bfloat16* __restrict__ Ch, __nv_bfloat16* __restrict__ Cl,
    int K, int N, long sA, long sB, long sC)
{
    extern __shared__ char dynsmem[];
    const uint32_t sbase = smem_u32(dynsmem);

    const int tid = threadIdx.x;
    const int wid = tid >> 5, lane = tid & 31;
    const long z = blockIdx.z;
    Ah += z * sA;  Al += z * sA;
    Bh += z * sB;  Bl += z * sB;

    const int tileM = blockIdx.y * 128;
    const int tileN = blockIdx.x * 128;
    const int wm = (wid >> 2) * 64;      // warp M offset in tile
    const int wn = (wid & 3) * 32;       // warp N offset in tile

    const int NCH = K / BK;

    // ---- loader: 2048 x 16B granules per stage ----
    auto load_stage = [&](int c, int s) {
        const uint32_t st = sbase + s * STAGE_BYTES;
        const long kb = (long)c * BK;
#pragma unroll
        for (int it = 0; it < 8; it++) {
            int g = it * 256 + tid;
            int which = g >> 9;          // 0:Ah 1:Al 2:Bh 3:Bl
            int r = (g >> 2) & 127;
            int c16 = g & 3;
            uint32_t dst = st + which * (128 * RSTRIDE) + r * RSTRIDE + c16 * 16;
            const __nv_bfloat16* src;
            if (which == 0)      src = Ah + (long)(tileM + r) * K + kb + c16 * 8;
            else if (which == 1) src = Al + (long)(tileM + r) * K + kb + c16 * 8;
            else if (which == 2) src = Bh + (long)(tileN + r) * K + kb + c16 * 8;
            else                 src = Bl + (long)(tileN + r) * K + kb + c16 * 8;
            cp16(dst, src);
        }
        cp_commit();
    };

    float acc[4][4][4];
#pragma unroll
    for (int i = 0; i < 4; i++)
#pragma unroll
        for (int j = 0; j < 4; j++)
#pragma unroll
            for (int t = 0; t < 4; t++) acc[i][j][t] = 0.f;

    load_stage(0, 0);
    load_stage(1, 1);

    const int lr = lane & 15;            // ldmatrix row-within-16
    const int lc = lane >> 4;            // ldmatrix k-half

    for (int c = 0; c < NCH; c++) {
        cp_wait<1>();
        __syncthreads();
        if (c + 2 < NCH) load_stage(c + 2, (c + 2) % NSTAGES);

        const uint32_t st = sbase + (c % NSTAGES) * STAGE_BYTES;
        const uint32_t sa_h = st + SA_H, sa_l = st + SA_L;
        const uint32_t sb_h = st + SB_H, sb_l = st + SB_L;

#pragma unroll
        for (int kk = 0; kk < 2; kk++) {
            const uint32_t koff = kk * 32 + lc * 16;
            // B fragments: 2 n16 groups -> 4 n8 blocks, hi + lo
            uint32_t bh[2][4], bl[2][4];
#pragma unroll
            for (int g = 0; g < 2; g++) {
                uint32_t ro = (uint32_t)(wn + g * 16 + lr) * RSTRIDE + koff;
                ldm_x4(bh[g], sb_h + ro);
                ldm_x4(bl[g], sb_l + ro);
            }
#pragma unroll
            for (int mi = 0; mi < 4; mi++) {
                uint32_t ro = (uint32_t)(wm + mi * 16 + lr) * RSTRIDE + koff;
                uint32_t ah[4], al[4];
                ldm_x4(ah, sa_h + ro);
                ldm_x4(al, sa_l + ro);
#pragma unroll
                for (int ni = 0; ni < 4; ni++) {
                    const int g = ni >> 1, o = ni & 1;   // n16 group, n8 within
                    const uint32_t b0h = bh[g][o], b1h = bh[g][o + 2];
                    const uint32_t b0l = bl[g][o], b1l = bl[g][o + 2];
                    mma_bf16(acc[mi][ni], ah, b0h, b1h);
                    mma_bf16(acc[mi][ni], ah, b0l, b1l);
                    mma_bf16(acc[mi][ni], al, b0h, b1h);
                }
            }
        }
        __syncthreads();
    }
    cp_wait<0>();

    // ---- epilogue ----
    const int er = lane >> 2;            // 0..7
    const int ec = (lane & 3) * 2;       // 0,2,4,6
#pragma unroll
    for (int mi = 0; mi < 4; mi++) {
#pragma unroll
        for (int ni = 0; ni < 4; ni++) {
            const int col = tileN + wn + ni * 8 + ec;
            const long r0 = tileM + wm + mi * 16 + er;
            const float b0 = __ldg(bias + col), b1 = __ldg(bias + col + 1);
            float v0 = acc[mi][ni][0] + b0, v1 = acc[mi][ni][1] + b1;
            float v2 = acc[mi][ni][2] + b0, v3 = acc[mi][ni][3] + b1;
            if (ACT) {
                v0 = act_elu1(v0); v1 = act_elu1(v1);
                v2 = act_elu1(v2); v3 = act_elu1(v3);
            }
            if (OUTBF) {
                __nv_bfloat16 h0 = __float2bfloat16(v0), h1 = __float2bfloat16(v1);
                __nv_bfloat16 h2 = __float2bfloat16(v2), h3 = __float2bfloat16(v3);
                *(uint32_t*)(Ch + r0 * N + col) =
                    (uint32_t)__bfloat16_as_ushort(h0) | ((uint32_t)__bfloat16_as_ushort(h1) << 16);
                *(uint32_t*)(Ch + (r0 + 8) * N + col) =
                    (uint32_t)__bfloat16_as_ushort(h2) | ((uint32_t)__bfloat16_as_ushort(h3) << 16);
                *(uint32_t*)(Cl + r0 * N + col) =
                    bfpack(v0 - __bfloat162float(h0), v1 - __bfloat162float(h1));
                *(uint32_t*)(Cl + (r0 + 8) * N + col) =
                    bfpack(v2 - __bfloat162float(h2), v3 - __bfloat162float(h3));
            } else {
                float* o = Cf + z * sC;
                *(float2*)(o + r0 * N + col) = make_float2(v0, v1);
                *(float2*)(o + (r0 + 8) * N + col) = make_float2(v2, v3);
            }
        }
    }
}

// ---------------- P = RF @ RF^T (64x64) ------------------------------------
__global__ __launch_bounds__(256) void pmat_kernel(const float* __restrict__ RF,
                                                   float* __restrict__ P)
{
    __shared__ float RFs[64][65];
    const int tid = threadIdx.x;
    const int i  = tid / 4;
    const int j0 = (tid % 4) * 16;
    float acc[16];
#pragma unroll
    for (int j = 0; j < 16; j++) acc[j] = 0.f;

    for (int f0 = 0; f0 < FEAT; f0 += 64) {
        for (int t = tid; t < 64 * 16; t += 256) {
            int r = t / 16, c4 = (t % 16) * 4;
            float4 v = *(const float4*)(RF + (long)r * FEAT + f0 + c4);
            RFs[r][c4 + 0] = v.x;
            RFs[r][c4 + 1] = v.y;
            RFs[r][c4 + 2] = v.z;
            RFs[r][c4 + 3] = v.w;
        }
        __syncthreads();
#pragma unroll 8
        for (int f = 0; f < 64; f++) {
            float a = RFs[i][f];
#pragma unroll
            for (int j = 0; j < 16; j++)
                acc[j] = fmaf(a, RFs[j0 + j][f], acc[j]);
        }
        __syncthreads();
    }
#pragma unroll
    for (int j = 0; j < 16; j++) P[i * HD + j0 + j] = acc[j];
}

// ---------------- G partials: G(b,h) += k1[chunk]^T @ v[chunk] --------------
__global__ __launch_bounds__(256) void kv_outer_kernel(const float* __restrict__ Kmat,
                                                       const float* __restrict__ Vmat,
                                                       float* __restrict__ Gp)
{
    const int bh = blockIdx.x;
    const int b = bh / HEADS, h = bh % HEADS;
    const int split = blockIdx.y;
    const int n0 = split * (NLEN / GSPLIT);
    const int CH = 32;

    __shared__ float Ks[CH][HD];
    __shared__ float Vs[CH][HD];

    const int tid = threadIdx.x;
    const int ty = tid / 16, tx = tid % 16;
    float acc[4][4];
#pragma unroll
    for (int i = 0; i < 4; i++)
#pragma unroll
        for (int j = 0; j < 4; j++) acc[i][j] = 0.f;

    const long base = ((long)b * NLEN) * DIM_ + h * HD;

    for (int n = n0; n < n0 + NLEN / GSPLIT; n += CH) {
        for (int t = tid; t < CH * 16; t += 256) {
            int r = t / 16, c4 = (t % 16) * 4;
            *(float4*)&Ks[r][c4] = *(const float4*)(Kmat + base + (long)(n + r) * DIM_ + c4);
            *(float4*)&Vs[r][c4] = *(const float4*)(Vmat + base + (long)(n + r) * DIM_ + c4);
        }
        __syncthreads();
#pragma unroll
        for (int kk = 0; kk < CH; kk++) {
            float kr[4], vr[4];
#pragma unroll
            for (int i = 0; i < 4; i++) kr[i] = Ks[kk][ty * 4 + i];
#pragma unroll
            for (int j = 0; j < 4; j++) vr[j] = Vs[kk][tx * 4 + j];
#pragma unroll
            for (int i = 0; i < 4; i++)
#pragma unroll
                for (int j = 0; j < 4; j++)
                    acc[i][j] = fmaf(kr[i], vr[j], acc[i][j]);
        }
        __syncthreads();
    }

    float* out = Gp + ((long)split * BSZ * HEADS + bh) * HD * HD;
#pragma unroll
    for (int i = 0; i < 4; i++)
#pragma unroll
        for (int j = 0; j < 4; j++)
            out[(ty * 4 + i) * HD + tx * 4 + j] = acc[i][j];
}

// ---------------- reduce G partials, M = P @ G ------------------------------
__global__ __launch_bounds__(256) void gm_kernel(const float* __restrict__ Gp,
                                                 const float* __restrict__ P,
                                                 float* __restrict__ Mout)
{
    const int bh = blockIdx.x;
    __shared__ float Gs[HD][HD];
    __shared__ float Ps[HD][HD];
    const int tid = threadIdx.x;

    for (int t = tid; t < HD * HD; t += 256) {
        float s = 0.f;
#pragma unroll
        for (int sp = 0; sp < GSPLIT; sp++)
            s += Gp[((long)sp * BSZ * HEADS + bh) * HD * HD + t];
        Gs[t / HD][t % HD] = s;
        Ps[t / HD][t % HD] = P[t];
    }
    __syncthreads();

    const int e = tid / 4;
    const int d0 = (tid % 4) * 16;
    float acc[16];
#pragma unroll
    for (int j = 0; j < 16; j++) acc[j] = 0.f;
#pragma unroll 8
    for (int c = 0; c < HD; c++) {
        float pe = Ps[e][c];
#pragma unroll
        for (int j = 0; j < 16; j++)
            acc[j] = fmaf(pe, Gs[c][d0 + j], acc[j]);
    }
#pragma unroll
    for (int j = 0; j < 16; j++)
        Mout[(long)bh * HD * HD + e * HD + d0 + j] = acc[j];
}

// ---------------- W2t(b)[c, h*64+e] = sum_d M(b,h)[e,d] * Wo[h*64+d, c] -----
__global__ __launch_bounds__(256) void w2_kernel(const float* __restrict__ Mmat,
                                                 const float* __restrict__ Wo,
                                                 __nv_bfloat16* __restrict__ W2th,
                                                 __nv_bfloat16* __restrict__ W2tl)
{
    const int bh = blockIdx.x;
    const int b = bh / HEADS, h = bh % HEADS;
    const int c0 = blockIdx.y * 128;

    __shared__ float Ms[HD][HD];
    const int tid = threadIdx.x;
    for (int t = tid; t < HD * HD; t += 256)
        Ms[t / HD][t % HD] = Mmat[(long)bh * HD * HD + t];
    __syncthreads();

    const int col = c0 + (tid & 127);
    const int e0  = (tid >> 7) * 32;
    float acc[32];
#pragma unroll
    for (int e = 0; e < 32; e++) acc[e] = 0.f;
#pragma unroll 4
    for (int d = 0; d < HD; d++) {
        float w = Wo[(long)(h * HD + d) * DIM_ + col];
#pragma unroll
        for (int e = 0; e < 32; e++)
            acc[e] = fmaf(Ms[e0 + e][d], w, acc[e]);
    }
    const long obase = (long)b * DIM_ * DIM_ + (long)col * DIM_ + h * HD + e0;
#pragma unroll
    for (int e = 0; e < 32; e++) {
        __nv_bfloat16 hh = __float2bfloat16(acc[e]);
        W2th[obase + e] = hh;
        W2tl[obase + e] = __float2bfloat16(acc[e] - __bfloat162float(hh));
    }
}

// ---------------- launch ----------------------------------------------------
extern "C" void kernel_launch(void* const* d_in, const int* in_sizes, int n_in,
                              void* d_out, int out_size)
{
    const float* x   = (const float*)d_in[0];
    const float* Wq  = (const float*)d_in[1];
    const float* bq  = (const float*)d_in[2];
    const float* Wk  = (const float*)d_in[3];
    const float* bk  = (const float*)d_in[4];
    const float* Wv  = (const float*)d_in[5];
    const float* bv  = (const float*)d_in[6];
    const float* Wo  = (const float*)d_in[7];
    const float* bo  = (const float*)d_in[8];
    const float* RF  = (const float*)d_in[9];
    float* out = (float*)d_out;

    __nv_bfloat16 *xh, *xl, *q1h, *q1l, *wth, *wtl, *w2th, *w2tl;
    float *kp, *vp, *gpp, *pp, *mp;
    cudaGetSymbolAddress((void**)&xh,   g_xh);
    cudaGetSymbolAddress((void**)&xl,   g_xl);
    cudaGetSymbolAddress((void**)&q1h,  g_q1h);
    cudaGetSymbolAddress((void**)&q1l,  g_q1l);
    cudaGetSymbolAddress((void**)&kp,   g_k);
    cudaGetSymbolAddress((void**)&vp,   g_v);
    cudaGetSymbolAddress((void**)&wth,  g_wth);
    cudaGetSymbolAddress((void**)&wtl,  g_wtl);
    cudaGetSymbolAddress((void**)&w2th, g_w2th);
    cudaGetSymbolAddress((void**)&w2tl, g_w2tl);
    cudaGetSymbolAddress((void**)&gpp,  g_Gpart);
    cudaGetSymbolAddress((void**)&pp,   g_P);
    cudaGetSymbolAddress((void**)&mp,   g_M);

    cudaFuncSetAttribute(gemm_tc<1, 1>, cudaFuncAttributeMaxDynamicSharedMemorySize, GEMM_SMEM);
    cudaFuncSetAttribute(gemm_tc<1, 0>, cudaFuncAttributeMaxDynamicSharedMemorySize, GEMM_SMEM);
    cudaFuncSetAttribute(gemm_tc<0, 0>, cudaFuncAttributeMaxDynamicSharedMemorySize, GEMM_SMEM);

    const size_t WSZ = (size_t)DIM_ * DIM_;

    // 1) split x into bf16 hi/lo (shared A for all 3 projections)
    conv_x_kernel<<<(ROWS * DIM_ / 4 + 255) / 256, 256>>>(
        (const float4*)x, (uint2*)xh, (uint2*)xl, ROWS * DIM_ / 4);

    // 2) transpose + split weights
    dim3 wgrid(32, 32), wblk(32, 32);
    conv_w_kernel<<<wgrid, wblk>>>(Wq, wth + 0 * WSZ, wtl + 0 * WSZ);
    conv_w_kernel<<<wgrid, wblk>>>(Wk, wth + 1 * WSZ, wtl + 1 * WSZ);
    conv_w_kernel<<<wgrid, wblk>>>(Wv, wth + 2 * WSZ, wtl + 2 * WSZ);

    // 3) QKV projections on tensor cores (bf16x3 via mma.sync)
    dim3 gq(DIM_ / 128, ROWS / 128, 1);
    gemm_tc<1, 1><<<gq, 256, GEMM_SMEM>>>(xh, xl, wth + 0 * WSZ, wtl + 0 * WSZ, bq,
                                          nullptr, q1h, q1l, DIM_, DIM_, 0, 0, 0);
    gemm_tc<1, 0><<<gq, 256, GEMM_SMEM>>>(xh, xl, wth + 1 * WSZ, wtl + 1 * WSZ, bk,
                                          kp, nullptr, nullptr, DIM_, DIM_, 0, 0, 0);
    gemm_tc<0, 0><<<gq, 256, GEMM_SMEM>>>(xh, xl, wth + 2 * WSZ, wtl + 2 * WSZ, bv,
                                          vp, nullptr, nullptr, DIM_, DIM_, 0, 0, 0);

    // 4) P = RF @ RF^T
    pmat_kernel<<<1, 256>>>(RF, pp);

    // 5) G partials: k1^T v per (b,h)
    kv_outer_kernel<<<dim3(BSZ * HEADS, GSPLIT), 256>>>(kp, vp, gpp);

    // 6) reduce + M = P @ G
    gm_kernel<<<BSZ * HEADS, 256>>>(gpp, pp, mp);

    // 7) W2t(b) = (blockdiag(M) @ Wo)^T, bf16 hi/lo
    w2_kernel<<<dim3(BSZ * HEADS, DIM_ / 128), 256>>>(mp, Wo, w2th, w2tl);

    // 8) final: out(b) = q1(b) @ W2(b) + bo (batched, tensor cores)
    dim3 gf(DIM_ / 128, NLEN / 128, BSZ);
    gemm_tc<0, 0><<<gf, 256, GEMM_SMEM>>>(q1h, q1l, w2th, w2tl, bo,
                                          out, nullptr, nullptr, DIM_, DIM_,
                                          (long)NLEN * DIM_, (long)DIM_ * DIM_,
                                          (long)NLEN * DIM_);
}

// round 7
// speedup vs baseline: 2.1364x; 1.1294x over previous
#include <cuda_runtime.h>
#include <cuda_bf16.h>
#include <cstdint>
#include <math.h>

// Problem constants
#define BSZ   4
#define NLEN  4096
#define DIM_  1024
#define HEADS 16
#define HD    64
#define FEAT  256
#define ROWS  (BSZ * NLEN)   // 16384
#define GSPLIT 8

// ---------------- scratch (__device__ globals; no allocation allowed) ------
__device__ __align__(16) __nv_bfloat16 g_xh[(size_t)ROWS * DIM_];
__device__ __align__(16) __nv_bfloat16 g_xl[(size_t)ROWS * DIM_];
__device__ __align__(16) __nv_bfloat16 g_q1h[(size_t)ROWS * DIM_];
__device__ __align__(16) __nv_bfloat16 g_q1l[(size_t)ROWS * DIM_];
__device__ __align__(16) float g_k[(size_t)ROWS * DIM_];
__device__ __align__(16) float g_v[(size_t)ROWS * DIM_];
__device__ __align__(16) __nv_bfloat16 g_wth[3][(size_t)DIM_ * DIM_];   // W^T hi
__device__ __align__(16) __nv_bfloat16 g_wtl[3][(size_t)DIM_ * DIM_];   // W^T lo
__device__ __align__(16) __nv_bfloat16 g_w2th[(size_t)BSZ * DIM_ * DIM_];
__device__ __align__(16) __nv_bfloat16 g_w2tl[(size_t)BSZ * DIM_ * DIM_];
__device__ float g_Gpart[(size_t)GSPLIT * BSZ * HEADS * HD * HD];
__device__ float g_P[HD * HD];
__device__ float g_M[(size_t)BSZ * HEADS * HD * HD];

__device__ __forceinline__ float act_elu1(float x) {
    return x > 0.f ? x + 1.f : expf(x);
}

// ======================= PTX helpers (non-'a' ISA only) =====================
__device__ __forceinline__ uint32_t smem_u32(const void* p) {
    return (uint32_t)__cvta_generic_to_shared(p);
}

__device__ __forceinline__ void cp16(uint32_t smem, const void* g) {
    asm volatile("cp.async.cg.shared.global [%0], [%1], 16;\n" :: "r"(smem), "l"(g));
}
__device__ __forceinline__ void cp_commit() {
    asm volatile("cp.async.commit_group;\n" ::: "memory");
}
template <int N>
__device__ __forceinline__ void cp_wait() {
    asm volatile("cp.async.wait_group %0;\n" :: "n"(N) : "memory");
}

__device__ __forceinline__ void ldm_x4(uint32_t* r, uint32_t addr) {
    asm volatile("ldmatrix.sync.aligned.m8n8.x4.shared.b16 {%0,%1,%2,%3}, [%4];"
                 : "=r"(r[0]), "=r"(r[1]), "=r"(r[2]), "=r"(r[3]) : "r"(addr));
}

__device__ __forceinline__ void mma_bf16(float* c, const uint32_t* a, uint32_t b0, uint32_t b1) {
    asm volatile(
        "mma.sync.aligned.m16n8k16.row.col.f32.bf16.bf16.f32 "
        "{%0,%1,%2,%3}, {%4,%5,%6,%7}, {%8,%9}, {%0,%1,%2,%3};"
        : "+f"(c[0]), "+f"(c[1]), "+f"(c[2]), "+f"(c[3])
        : "r"(a[0]), "r"(a[1]), "r"(a[2]), "r"(a[3]), "r"(b0), "r"(b1));
}

__device__ __forceinline__ uint32_t bfpack(float a, float b) {
    __nv_bfloat16 h0 = __float2bfloat16(a), h1 = __float2bfloat16(b);
    return (uint32_t)__bfloat16_as_ushort(h0) | ((uint32_t)__bfloat16_as_ushort(h1) << 16);
}

// ======================= conversion kernels ================================
__global__ __launch_bounds__(256) void conv_x_kernel(const float4* __restrict__ x,
                                                     uint2* __restrict__ xh,
                                                     uint2* __restrict__ xl, int n4)
{
    int i = blockIdx.x * 256 + threadIdx.x;
    if (i >= n4) return;
    float4 v = x[i];
    __nv_bfloat16 h0 = __float2bfloat16(v.x), h1 = __float2bfloat16(v.y);
    __nv_bfloat16 h2 = __float2bfloat16(v.z), h3 = __float2bfloat16(v.w);
    uint2 H, L;
    H.x = (uint32_t)__bfloat16_as_ushort(h0) | ((uint32_t)__bfloat16_as_ushort(h1) << 16);
    H.y = (uint32_t)__bfloat16_as_ushort(h2) | ((uint32_t)__bfloat16_as_ushort(h3) << 16);
    L.x = bfpack(v.x - __bfloat162float(h0), v.y - __bfloat162float(h1));
    L.y = bfpack(v.z - __bfloat162float(h2), v.w - __bfloat162float(h3));
    xh[i] = H;
    xl[i] = L;
}

// transpose + split: Wt[n,k] = W[k,n]
__global__ __launch_bounds__(1024) void conv_w_kernel(const float* __restrict__ W,
                                                      __nv_bfloat16* __restrict__ Wth,
                                                      __nv_bfloat16* __restrict__ Wtl)
{
    __shared__ float t[32][33];
    int tx = threadIdx.x, ty = threadIdx.y;
    int k = blockIdx.y * 32 + ty, n = blockIdx.x * 32 + tx;
    t[ty][tx] = W[(long)k * DIM_ + n];
    __syncthreads();
    float v = t[tx][ty];
    long o = (long)(blockIdx.x * 32 + ty) * DIM_ + blockIdx.y * 32 + tx;
    __nv_bfloat16 h = __float2bfloat16(v);
    Wth[o] = h;
    Wtl[o] = __float2bfloat16(v - __bfloat162float(h));
}

// ======================= mma.sync bf16x3 GEMM ===============================
// C(M x N) = A(M x K) @ Bt(N x K)^T + bias.  A/B in bf16 hi/lo pairs, K-major.
// Block tile 128x128, BK=32, 8 warps (warp tile 64x32), 2-stage cp.async.
// Stage = 40KB; 2 stages = 80KB -> 2 CTAs/SM (16 warps).
#define BK 32
#define RSTRIDE 80                       // 64B row + 16B pad (conflict-free ldmatrix)
#define SA_H 0
#define SA_L (128 * RSTRIDE)
#define SB_H (2 * 128 * RSTRIDE)
#define SB_L (3 * 128 * RSTRIDE)
#define STAGE_BYTES (4 * 128 * RSTRIDE)  // 40960
#define NSTAGES 2
#define GEMM_SMEM (NSTAGES * STAGE_BYTES)

template <int ACT, int OUTBF>
__global__ __launch_bounds__(256, 2) void gemm_tc(
    const __nv_bfloat16* __restrict__ Ah, const __nv_bfloat16* __restrict__ Al,
    const __nv_bfloat16* __restrict__ Bh, const __nv_bfloat16* __restrict__ Bl,
    const float* __restrict__ bias,
    float* __restrict__ Cf, __nv_bfloat16* __restrict__ Ch, __nv_bfloat16* __restrict__ Cl,
    int K, int N, long sA, long sB, long sC)
{
    extern __shared__ char dynsmem[];
    const uint32_t sbase = smem_u32(dynsmem);

    const int tid = threadIdx.x;
    const int wid = tid >> 5, lane = tid & 31;
    const long z = blockIdx.z;
    Ah += z * sA;  Al += z * sA;
    Bh += z * sB;  Bl += z * sB;

    const int tileM = blockIdx.y * 128;
    const int tileN = blockIdx.x * 128;
    const int wm = (wid >> 2) * 64;      // warp M offset in tile
    const int wn = (wid & 3) * 32;       // warp N offset in tile

    const int NCH = K / BK;

    // ---- loader: 2048 x 16B granules per stage ----
    auto load_stage = [&](int c, int s) {
        const uint32_t st = sbase + s * STAGE_BYTES;
        const long kb = (long)c * BK;
#pragma unroll
        for (int it = 0; it < 8; it++) {
            int g = it * 256 + tid;
            int which = g >> 9;          // 0:Ah 1:Al 2:Bh 3:Bl
            int r = (g >> 2) & 127;
            int c16 = g & 3;
            uint32_t dst = st + which * (128 * RSTRIDE) + r * RSTRIDE + c16 * 16;
            const __nv_bfloat16* src;
            if (which == 0)      src = Ah + (long)(tileM + r) * K + kb + c16 * 8;
            else if (which == 1) src = Al + (long)(tileM + r) * K + kb + c16 * 8;
            else if (which == 2) src = Bh + (long)(tileN + r) * K + kb + c16 * 8;
            else                 src = Bl + (long)(tileN + r) * K + kb + c16 * 8;
            cp16(dst, src);
        }
        cp_commit();
    };

    float acc[4][4][4];
#pragma unroll
    for (int i = 0; i < 4; i++)
#pragma unroll
        for (int j = 0; j < 4; j++)
#pragma unroll
            for (int t = 0; t < 4; t++) acc[i][j][t] = 0.f;

    load_stage(0, 0);

    const int lr = lane & 15;            // ldmatrix row-within-16
    const int lc = lane >> 4;            // ldmatrix k-half

    for (int c = 0; c < NCH; c++) {
        // issue next stage first, then wait so that stage c is provably complete:
        // after the issue, the newest pending group is c+1's; wait<1> retires all
        // older groups (including stage c). Last iteration: full drain.
        if (c + 1 < NCH) { load_stage(c + 1, (c + 1) & 1); cp_wait<1>(); }
        else             { cp_wait<0>(); }
        __syncthreads();

        const uint32_t st = sbase + (c & 1) * STAGE_BYTES;
        const uint32_t sa_h = st + SA_H, sa_l = st + SA_L;
        const uint32_t sb_h = st + SB_H, sb_l = st + SB_L;

#pragma unroll
        for (int kk = 0; kk < 2; kk++) {
            const uint32_t koff = kk * 32 + lc * 16;
            // B fragments: 2 n16 groups -> 4 n8 blocks, hi + lo
            uint32_t bh[2][4], bl[2][4];
#pragma unroll
            for (int g = 0; g < 2; g++) {
                uint32_t ro = (uint32_t)(wn + g * 16 + lr) * RSTRIDE + koff;
                ldm_x4(bh[g], sb_h + ro);
                ldm_x4(bl[g], sb_l + ro);
            }
#pragma unroll
            for (int mi = 0; mi < 4; mi++) {
                uint32_t ro = (uint32_t)(wm + mi * 16 + lr) * RSTRIDE + koff;
                uint32_t ah[4], al[4];
                ldm_x4(ah, sa_h + ro);
                ldm_x4(al, sa_l + ro);
#pragma unroll
                for (int ni = 0; ni < 4; ni++) {
                    const int g = ni >> 1, o = ni & 1;   // n16 group, n8 within
                    const uint32_t b0h = bh[g][o], b1h = bh[g][o + 2];
                    const uint32_t b0l = bl[g][o], b1l = bl[g][o + 2];
                    mma_bf16(acc[mi][ni], ah, b0h, b1h);
                    mma_bf16(acc[mi][ni], ah, b0l, b1l);
                    mma_bf16(acc[mi][ni], al, b0h, b1h);
                }
            }
        }
        __syncthreads();
    }

    // ---- epilogue ----
    const int er = lane >> 2;            // 0..7
    const int ec = (lane & 3) * 2;       // 0,2,4,6
#pragma unroll
    for (int mi = 0; mi < 4; mi++) {
#pragma unroll
        for (int ni = 0; ni < 4; ni++) {
            const int col = tileN + wn + ni * 8 + ec;
            const long r0 = tileM + wm + mi * 16 + er;
            const float b0 = __ldg(bias + col), b1 = __ldg(bias + col + 1);
            float v0 = acc[mi][ni][0] + b0, v1 = acc[mi][ni][1] + b1;
            float v2 = acc[mi][ni][2] + b0, v3 = acc[mi][ni][3] + b1;
            if (ACT) {
                v0 = act_elu1(v0); v1 = act_elu1(v1);
                v2 = act_elu1(v2); v3 = act_elu1(v3);
            }
            if (OUTBF) {
                __nv_bfloat16 h0 = __float2bfloat16(v0), h1 = __float2bfloat16(v1);
                __nv_bfloat16 h2 = __float2bfloat16(v2), h3 = __float2bfloat16(v3);
                *(uint32_t*)(Ch + r0 * N + col) =
                    (uint32_t)__bfloat16_as_ushort(h0) | ((uint32_t)__bfloat16_as_ushort(h1) << 16);
                *(uint32_t*)(Ch + (r0 + 8) * N + col) =
                    (uint32_t)__bfloat16_as_ushort(h2) | ((uint32_t)__bfloat16_as_ushort(h3) << 16);
                *(uint32_t*)(Cl + r0 * N + col) =
                    bfpack(v0 - __bfloat162float(h0), v1 - __bfloat162float(h1));
                *(uint32_t*)(Cl + (r0 + 8) * N + col) =
                    bfpack(v2 - __bfloat162float(h2), v3 - __bfloat162float(h3));
            } else {
                float* o = Cf + z * sC;
                *(float2*)(o + r0 * N + col) = make_float2(v0, v1);
                *(float2*)(o + (r0 + 8) * N + col) = make_float2(v2, v3);
            }
        }
    }
}

// ---------------- P = RF @ RF^T (64x64) ------------------------------------
__global__ __launch_bounds__(256) void pmat_kernel(const float* __restrict__ RF,
                                                   float* __restrict__ P)
{
    __shared__ float RFs[64][65];
    const int tid = threadIdx.x;
    const int i  = tid / 4;
    const int j0 = (tid % 4) * 16;
    float acc[16];
#pragma unroll
    for (int j = 0; j < 16; j++) acc[j] = 0.f;

    for (int f0 = 0; f0 < FEAT; f0 += 64) {
        for (int t = tid; t < 64 * 16; t += 256) {
            int r = t / 16, c4 = (t % 16) * 4;
            float4 v = *(const float4*)(RF + (long)r * FEAT + f0 + c4);
            RFs[r][c4 + 0] = v.x;
            RFs[r][c4 + 1] = v.y;
            RFs[r][c4 + 2] = v.z;
            RFs[r][c4 + 3] = v.w;
        }
        __syncthreads();
#pragma unroll 8
        for (int f = 0; f < 64; f++) {
            float a = RFs[i][f];
#pragma unroll
            for (int j = 0; j < 16; j++)
                acc[j] = fmaf(a, RFs[j0 + j][f], acc[j]);
        }
        __syncthreads();
    }
#pragma unroll
    for (int j = 0; j < 16; j++) P[i * HD + j0 + j] = acc[j];
}

// ---------------- G partials: G(b,h) += k1[chunk]^T @ v[chunk] --------------
__global__ __launch_bounds__(256) void kv_outer_kernel(const float* __restrict__ Kmat,
                                                       const float* __restrict__ Vmat,
                                                       float* __restrict__ Gp)
{
    const int bh = blockIdx.x;
    const int b = bh / HEADS, h = bh % HEADS;
    const int split = blockIdx.y;
    const int n0 = split * (NLEN / GSPLIT);
    const int CH = 32;

    __shared__ float Ks[CH][HD];
    __shared__ float Vs[CH][HD];

    const int tid = threadIdx.x;
    const int ty = tid / 16, tx = tid % 16;
    float acc[4][4];
#pragma unroll
    for (int i = 0; i < 4; i++)
#pragma unroll
        for (int j = 0; j < 4; j++) acc[i][j] = 0.f;

    const long base = ((long)b * NLEN) * DIM_ + h * HD;

    for (int n = n0; n < n0 + NLEN / GSPLIT; n += CH) {
        for (int t = tid; t < CH * 16; t += 256) {
            int r = t / 16, c4 = (t % 16) * 4;
            *(float4*)&Ks[r][c4] = *(const float4*)(Kmat + base + (long)(n + r) * DIM_ + c4);
            *(float4*)&Vs[r][c4] = *(const float4*)(Vmat + base + (long)(n + r) * DIM_ + c4);
        }
        __syncthreads();
#pragma unroll
        for (int kk = 0; kk < CH; kk++) {
            float kr[4], vr[4];
#pragma unroll
            for (int i = 0; i < 4; i++) kr[i] = Ks[kk][ty * 4 + i];
#pragma unroll
            for (int j = 0; j < 4; j++) vr[j] = Vs[kk][tx * 4 + j];
#pragma unroll
            for (int i = 0; i < 4; i++)
#pragma unroll
                for (int j = 0; j < 4; j++)
                    acc[i][j] = fmaf(kr[i], vr[j], acc[i][j]);
        }
        __syncthreads();
    }

    float* out = Gp + ((long)split * BSZ * HEADS + bh) * HD * HD;
#pragma unroll
    for (int i = 0; i < 4; i++)
#pragma unroll
        for (int j = 0; j < 4; j++)
            out[(ty * 4 + i) * HD + tx * 4 + j] = acc[i][j];
}

// ---------------- reduce G partials, M = P @ G ------------------------------
__global__ __launch_bounds__(256) void gm_kernel(const float* __restrict__ Gp,
                                                 const float* __restrict__ P,
                                                 float* __restrict__ Mout)
{
    const int bh = blockIdx.x;
    __shared__ float Gs[HD][HD];
    __shared__ float Ps[HD][HD];
    const int tid = threadIdx.x;

    for (int t = tid; t < HD * HD; t += 256) {
        float s = 0.f;
#pragma unroll
        for (int sp = 0; sp < GSPLIT; sp++)
            s += Gp[((long)sp * BSZ * HEADS + bh) * HD * HD + t];
        Gs[t / HD][t % HD] = s;
        Ps[t / HD][t % HD] = P[t];
    }
    __syncthreads();

    const int e = tid / 4;
    const int d0 = (tid % 4) * 16;
    float acc[16];
#pragma unroll
    for (int j = 0; j < 16; j++) acc[j] = 0.f;
#pragma unroll 8
    for (int c = 0; c < HD; c++) {
        float pe = Ps[e][c];
#pragma unroll
        for (int j = 0; j < 16; j++)
            acc[j] = fmaf(pe, Gs[c][d0 + j], acc[j]);
    }
#pragma unroll
    for (int j = 0; j < 16; j++)
        Mout[(long)bh * HD * HD + e * HD + d0 + j] = acc[j];
}

// ---------------- W2t(b)[c, h*64+e] = sum_d M(b,h)[e,d] * Wo[h*64+d, c] -----
__global__ __launch_bounds__(256) void w2_kernel(const float* __restrict__ Mmat,
                                                 const float* __restrict__ Wo,
                                                 __nv_bfloat16* __restrict__ W2th,
                                                 __nv_bfloat16* __restrict__ W2tl)
{
    const int bh = blockIdx.x;
    const int b = bh / HEADS, h = bh % HEADS;
    const int c0 = blockIdx.y * 128;

    __shared__ float Ms[HD][HD];
    const int tid = threadIdx.x;
    for (int t = tid; t < HD * HD; t += 256)
        Ms[t / HD][t % HD] = Mmat[(long)bh * HD * HD + t];
    __syncthreads();

    const int col = c0 + (tid & 127);
    const int e0  = (tid >> 7) * 32;
    float acc[32];
#pragma unroll
    for (int e = 0; e < 32; e++) acc[e] = 0.f;
#pragma unroll 4
    for (int d = 0; d < HD; d++) {
        float w = Wo[(long)(h * HD + d) * DIM_ + col];
#pragma unroll
        for (int e = 0; e < 32; e++)
            acc[e] = fmaf(Ms[e0 + e][d], w, acc[e]);
    }
    const long obase = (long)b * DIM_ * DIM_ + (long)col * DIM_ + h * HD + e0;
#pragma unroll
    for (int e = 0; e < 32; e++) {
        __nv_bfloat16 hh = __float2bfloat16(acc[e]);
        W2th[obase + e] = hh;
        W2tl[obase + e] = __float2bfloat16(acc[e] - __bfloat162float(hh));
    }
}

// ---------------- launch ----------------------------------------------------
extern "C" void kernel_launch(void* const* d_in, const int* in_sizes, int n_in,
                              void* d_out, int out_size)
{
    const float* x   = (const float*)d_in[0];
    const float* Wq  = (const float*)d_in[1];
    const float* bq  = (const float*)d_in[2];
    const float* Wk  = (const float*)d_in[3];
    const float* bk  = (const float*)d_in[4];
    const float* Wv  = (const float*)d_in[5];
    const float* bv  = (const float*)d_in[6];
    const float* Wo  = (const float*)d_in[7];
    const float* bo  = (const float*)d_in[8];
    const float* RF  = (const float*)d_in[9];
    float* out = (float*)d_out;

    __nv_bfloat16 *xh, *xl, *q1h, *q1l, *wth, *wtl, *w2th, *w2tl;
    float *kp, *vp, *gpp, *pp, *mp;
    cudaGetSymbolAddress((void**)&xh,   g_xh);
    cudaGetSymbolAddress((void**)&xl,   g_xl);
    cudaGetSymbolAddress((void**)&q1h,  g_q1h);
    cudaGetSymbolAddress((void**)&q1l,  g_q1l);
    cudaGetSymbolAddress((void**)&kp,   g_k);
    cudaGetSymbolAddress((void**)&vp,   g_v);
    cudaGetSymbolAddress((void**)&wth,  g_wth);
    cudaGetSymbolAddress((void**)&wtl,  g_wtl);
    cudaGetSymbolAddress((void**)&w2th, g_w2th);
    cudaGetSymbolAddress((void**)&w2tl, g_w2tl);
    cudaGetSymbolAddress((void**)&gpp,  g_Gpart);
    cudaGetSymbolAddress((void**)&pp,   g_P);
    cudaGetSymbolAddress((void**)&mp,   g_M);

    cudaFuncSetAttribute(gemm_tc<1, 1>, cudaFuncAttributeMaxDynamicSharedMemorySize, GEMM_SMEM);
    cudaFuncSetAttribute(gemm_tc<1, 0>, cudaFuncAttributeMaxDynamicSharedMemorySize, GEMM_SMEM);
    cudaFuncSetAttribute(gemm_tc<0, 0>, cudaFuncAttributeMaxDynamicSharedMemorySize, GEMM_SMEM);

    const size_t WSZ = (size_t)DIM_ * DIM_;

    // 1) split x into bf16 hi/lo (shared A for all 3 projections)
    conv_x_kernel<<<(ROWS * DIM_ / 4 + 255) / 256, 256>>>(
        (const float4*)x, (uint2*)xh, (uint2*)xl, ROWS * DIM_ / 4);

    // 2) transpose + split weights
    dim3 wgrid(32, 32), wblk(32, 32);
    conv_w_kernel<<<wgrid, wblk>>>(Wq, wth + 0 * WSZ, wtl + 0 * WSZ);
    conv_w_kernel<<<wgrid, wblk>>>(Wk, wth + 1 * WSZ, wtl + 1 * WSZ);
    conv_w_kernel<<<wgrid, wblk>>>(Wv, wth + 2 * WSZ, wtl + 2 * WSZ);

    // 3) QKV projections on tensor cores (bf16x3 via mma.sync)
    dim3 gq(DIM_ / 128, ROWS / 128, 1);
    gemm_tc<1, 1><<<gq, 256, GEMM_SMEM>>>(xh, xl, wth + 0 * WSZ, wtl + 0 * WSZ, bq,
                                          nullptr, q1h, q1l, DIM_, DIM_, 0, 0, 0);
    gemm_tc<1, 0><<<gq, 256, GEMM_SMEM>>>(xh, xl, wth + 1 * WSZ, wtl + 1 * WSZ, bk,
                                          kp, nullptr, nullptr, DIM_, DIM_, 0, 0, 0);
    gemm_tc<0, 0><<<gq, 256, GEMM_SMEM>>>(xh, xl, wth + 2 * WSZ, wtl + 2 * WSZ, bv,
                                          vp, nullptr, nullptr, DIM_, DIM_, 0, 0, 0);

    // 4) P = RF @ RF^T
    pmat_kernel<<<1, 256>>>(RF, pp);

    // 5) G partials: k1^T v per (b,h)
    kv_outer_kernel<<<dim3(BSZ * HEADS, GSPLIT), 256>>>(kp, vp, gpp);

    // 6) reduce + M = P @ G
    gm_kernel<<<BSZ * HEADS, 256>>>(gpp, pp, mp);

    // 7) W2t(b) = (blockdiag(M) @ Wo)^T, bf16 hi/lo
    w2_kernel<<<dim3(BSZ * HEADS, DIM_ / 128), 256>>>(mp, Wo, w2th, w2tl);

    // 8) final: out(b) = q1(b) @ W2(b) + bo (batched, tensor cores)
    dim3 gf(DIM_ / 128, NLEN / 128, BSZ);
    gemm_tc<0, 0><<<gf, 256, GEMM_SMEM>>>(q1h, q1l, w2th, w2tl, bo,
                                          out, nullptr, nullptr, DIM_, DIM_,
                                          (long)NLEN * DIM_, (long)DIM_ * DIM_,
                                          (long)NLEN * DIM_);
}

// round 8
// speedup vs baseline: 4.1301x; 1.9332x over previous
#include <cuda_runtime.h>
#include <cuda_fp16.h>
#include <cstdint>
#include <math.h>

// Problem constants
#define BSZ   4
#define NLEN  4096
#define DIM_  1024
#define HEADS 16
#define HD    64
#define FEAT  256
#define ROWS  (BSZ * NLEN)   // 16384
#define GSPLIT 8

// ---------------- scratch (__device__ globals; no allocation allowed) ------
__device__ __align__(16) __half g_x16[(size_t)ROWS * DIM_];
__device__ __align__(16) __half g_q116[(size_t)ROWS * DIM_];
__device__ __align__(16) float g_k[(size_t)ROWS * DIM_];
__device__ __align__(16) float g_v[(size_t)ROWS * DIM_];
__device__ __align__(16) __half g_wt16[3][(size_t)DIM_ * DIM_];   // W^T fp16
__device__ __align__(16) __half g_w2t16[(size_t)BSZ * DIM_ * DIM_];
__device__ float g_Gpart[(size_t)GSPLIT * BSZ * HEADS * HD * HD];
__device__ float g_P[HD * HD];
__device__ float g_M[(size_t)BSZ * HEADS * HD * HD];

__device__ __forceinline__ float act_elu1(float x) {
    return x > 0.f ? x + 1.f : expf(x);
}

// ======================= PTX helpers (non-'a' ISA only) =====================
__device__ __forceinline__ uint32_t smem_u32(const void* p) {
    return (uint32_t)__cvta_generic_to_shared(p);
}

__device__ __forceinline__ void cp16(uint32_t smem, const void* g) {
    asm volatile("cp.async.cg.shared.global [%0], [%1], 16;\n" :: "r"(smem), "l"(g));
}
__device__ __forceinline__ void cp_commit() {
    asm volatile("cp.async.commit_group;\n" ::: "memory");
}
template <int N>
__device__ __forceinline__ void cp_wait() {
    asm volatile("cp.async.wait_group %0;\n" :: "n"(N) : "memory");
}

__device__ __forceinline__ void ldm_x4(uint32_t* r, uint32_t addr) {
    asm volatile("ldmatrix.sync.aligned.m8n8.x4.shared.b16 {%0,%1,%2,%3}, [%4];"
                 : "=r"(r[0]), "=r"(r[1]), "=r"(r[2]), "=r"(r[3]) : "r"(addr));
}

__device__ __forceinline__ void mma_fp16(float* c, const uint32_t* a, uint32_t b0, uint32_t b1) {
    asm volatile(
        "mma.sync.aligned.m16n8k16.row.col.f32.f16.f16.f32 "
        "{%0,%1,%2,%3}, {%4,%5,%6,%7}, {%8,%9}, {%0,%1,%2,%3};"
        : "+f"(c[0]), "+f"(c[1]), "+f"(c[2]), "+f"(c[3])
        : "r"(a[0]), "r"(a[1]), "r"(a[2]), "r"(a[3]), "r"(b0), "r"(b1));
}

__device__ __forceinline__ uint32_t hpack(float a, float b) {
    __half h0 = __float2half_rn(a), h1 = __float2half_rn(b);
    return (uint32_t)__half_as_ushort(h0) | ((uint32_t)__half_as_ushort(h1) << 16);
}

// ======================= conversion kernels ================================
__global__ __launch_bounds__(256) void conv_x_kernel(const float4* __restrict__ x,
                                                     uint2* __restrict__ xo, int n4)
{
    int i = blockIdx.x * 256 + threadIdx.x;
    if (i >= n4) return;
    float4 v = x[i];
    uint2 H;
    H.x = hpack(v.x, v.y);
    H.y = hpack(v.z, v.w);
    xo[i] = H;
}

// transpose + fp16: Wt[n,k] = W[k,n]
__global__ __launch_bounds__(1024) void conv_w_kernel(const float* __restrict__ W,
                                                      __half* __restrict__ Wt)
{
    __shared__ float t[32][33];
    int tx = threadIdx.x, ty = threadIdx.y;
    int k = blockIdx.y * 32 + ty, n = blockIdx.x * 32 + tx;
    t[ty][tx] = W[(long)k * DIM_ + n];
    __syncthreads();
    float v = t[tx][ty];
    long o = (long)(blockIdx.x * 32 + ty) * DIM_ + blockIdx.y * 32 + tx;
    Wt[o] = __float2half_rn(v);
}

// ======================= mma.sync fp16 GEMM =================================
// C(M x N) = A(M x K) @ Bt(N x K)^T + bias.  A/B fp16, K-major.
// Block tile 128x128, BK=32, 8 warps (warp tile 64x32), 4-stage cp.async.
// Stage = 20KB; 4 stages = 80KB -> 2 CTAs/SM (16 warps).
#define BK 32
#define RSTRIDE 80                       // 64B row + 16B pad (conflict-free ldmatrix)
#define SA 0
#define SB (128 * RSTRIDE)
#define STAGE_BYTES (2 * 128 * RSTRIDE)  // 20480
#define NSTAGES 4
#define GEMM_SMEM (NSTAGES * STAGE_BYTES)

template <int ACT, int OUTHF>
__global__ __launch_bounds__(256, 2) void gemm_tc(
    const __half* __restrict__ Ax, const __half* __restrict__ Bx,
    const float* __restrict__ bias,
    float* __restrict__ Cf, __half* __restrict__ Chf,
    int K, int N, long sA, long sB, long sC)
{
    extern __shared__ char dynsmem[];
    const uint32_t sbase = smem_u32(dynsmem);

    const int tid = threadIdx.x;
    const int wid = tid >> 5, lane = tid & 31;
    const long z = blockIdx.z;
    Ax += z * sA;
    Bx += z * sB;

    const int tileM = blockIdx.y * 128;
    const int tileN = blockIdx.x * 128;
    const int wm = (wid >> 2) * 64;      // warp M offset in tile
    const int wn = (wid & 3) * 32;       // warp N offset in tile

    const int NCH = K / BK;

    // ---- loader: 1024 x 16B granules per stage (A + B, 128 rows x 4 segs) ----
    auto load_stage = [&](int c, int s) {
        const uint32_t st = sbase + s * STAGE_BYTES;
        const long kb = (long)c * BK;
#pragma unroll
        for (int it = 0; it < 4; it++) {
            int g = it * 256 + tid;
            int which = g >> 9;          // 0:A 1:B
            int r = (g >> 2) & 127;
            int c16 = g & 3;
            uint32_t dst = st + which * (128 * RSTRIDE) + r * RSTRIDE + c16 * 16;
            const __half* src = which ? (Bx + (long)(tileN + r) * K + kb + c16 * 8)
                                      : (Ax + (long)(tileM + r) * K + kb + c16 * 8);
            cp16(dst, src);
        }
        cp_commit();
    };

    float acc[4][4][4];
#pragma unroll
    for (int i = 0; i < 4; i++)
#pragma unroll
        for (int j = 0; j < 4; j++)
#pragma unroll
            for (int t = 0; t < 4; t++) acc[i][j][t] = 0.f;

    load_stage(0, 0);
    load_stage(1, 1);
    load_stage(2, 2);

    const int lr = lane & 15;            // ldmatrix row-within-16
    const int lc = lane >> 4;            // ldmatrix k-half

    for (int c = 0; c < NCH; c++) {
        // deep prefetch: issue stage c+3, then retire until stage c complete.
        if (c + 3 < NCH) { load_stage(c + 3, (c + 3) & 3); cp_wait<3>(); }
        else {
            const int rem = NCH - 1 - c;          // groups allowed pending
            if (rem >= 2)      cp_wait<2>();
            else if (rem == 1) cp_wait<1>();
            else               cp_wait<0>();
        }
        __syncthreads();

        const uint32_t st = sbase + (c & 3) * STAGE_BYTES;
        const uint32_t sa = st + SA, sb = st + SB;

#pragma unroll
        for (int kk = 0; kk < 2; kk++) {
            const uint32_t koff = kk * 32 + lc * 16;
            // B fragments: 2 n16 groups -> 4 n8 blocks
            uint32_t bh[2][4];
#pragma unroll
            for (int g = 0; g < 2; g++) {
                uint32_t ro = (uint32_t)(wn + g * 16 + lr) * RSTRIDE + koff;
                ldm_x4(bh[g], sb + ro);
            }
#pragma unroll
            for (int mi = 0; mi < 4; mi++) {
                uint32_t ro = (uint32_t)(wm + mi * 16 + lr) * RSTRIDE + koff;
                uint32_t ah[4];
                ldm_x4(ah, sa + ro);
#pragma unroll
                for (int ni = 0; ni < 4; ni++) {
                    const int g = ni >> 1, o = ni & 1;   // n16 group, n8 within
                    mma_fp16(acc[mi][ni], ah, bh[g][o], bh[g][o + 2]);
                }
            }
        }
        __syncthreads();
    }

    // ---- epilogue ----
    const int er = lane >> 2;            // 0..7
    const int ec = (lane & 3) * 2;       // 0,2,4,6
#pragma unroll
    for (int mi = 0; mi < 4; mi++) {
#pragma unroll
        for (int ni = 0; ni < 4; ni++) {
            const int col = tileN + wn + ni * 8 + ec;
            const long r0 = tileM + wm + mi * 16 + er;
            const float b0 = __ldg(bias + col), b1 = __ldg(bias + col + 1);
            float v0 = acc[mi][ni][0] + b0, v1 = acc[mi][ni][1] + b1;
            float v2 = acc[mi][ni][2] + b0, v3 = acc[mi][ni][3] + b1;
            if (ACT) {
                v0 = act_elu1(v0); v1 = act_elu1(v1);
                v2 = act_elu1(v2); v3 = act_elu1(v3);
            }
            if (OUTHF) {
                *(uint32_t*)(Chf + r0 * N + col)       = hpack(v0, v1);
                *(uint32_t*)(Chf + (r0 + 8) * N + col) = hpack(v2, v3);
            } else {
                float* o = Cf + z * sC;
                *(float2*)(o + r0 * N + col) = make_float2(v0, v1);
                *(float2*)(o + (r0 + 8) * N + col) = make_float2(v2, v3);
            }
        }
    }
}

// ---------------- P = RF @ RF^T (64x64) ------------------------------------
__global__ __launch_bounds__(256) void pmat_kernel(const float* __restrict__ RF,
                                                   float* __restrict__ P)
{
    __shared__ float RFs[64][65];
    const int tid = threadIdx.x;
    const int i  = tid / 4;
    const int j0 = (tid % 4) * 16;
    float acc[16];
#pragma unroll
    for (int j = 0; j < 16; j++) acc[j] = 0.f;

    for (int f0 = 0; f0 < FEAT; f0 += 64) {
        for (int t = tid; t < 64 * 16; t += 256) {
            int r = t / 16, c4 = (t % 16) * 4;
            float4 v = *(const float4*)(RF + (long)r * FEAT + f0 + c4);
            RFs[r][c4 + 0] = v.x;
            RFs[r][c4 + 1] = v.y;
            RFs[r][c4 + 2] = v.z;
            RFs[r][c4 + 3] = v.w;
        }
        __syncthreads();
#pragma unroll 8
        for (int f = 0; f < 64; f++) {
            float a = RFs[i][f];
#pragma unroll
            for (int j = 0; j < 16; j++)
                acc[j] = fmaf(a, RFs[j0 + j][f], acc[j]);
        }
        __syncthreads();
    }
#pragma unroll
    for (int j = 0; j < 16; j++) P[i * HD + j0 + j] = acc[j];
}

// ---------------- G partials: G(b,h) += k1[chunk]^T @ v[chunk] --------------
__global__ __launch_bounds__(256) void kv_outer_kernel(const float* __restrict__ Kmat,
                                                       const float* __restrict__ Vmat,
                                                       float* __restrict__ Gp)
{
    const int bh = blockIdx.x;
    const int b = bh / HEADS, h = bh % HEADS;
    const int split = blockIdx.y;
    const int n0 = split * (NLEN / GSPLIT);
    const int CH = 32;

    __shared__ float Ks[CH][HD];
    __shared__ float Vs[CH][HD];

    const int tid = threadIdx.x;
    const int ty = tid / 16, tx = tid % 16;
    float acc[4][4];
#pragma unroll
    for (int i = 0; i < 4; i++)
#pragma unroll
        for (int j = 0; j < 4; j++) acc[i][j] = 0.f;

    const long base = ((long)b * NLEN) * DIM_ + h * HD;

    for (int n = n0; n < n0 + NLEN / GSPLIT; n += CH) {
        for (int t = tid; t < CH * 16; t += 256) {
            int r = t / 16, c4 = (t % 16) * 4;
            *(float4*)&Ks[r][c4] = *(const float4*)(Kmat + base + (long)(n + r) * DIM_ + c4);
            *(float4*)&Vs[r][c4] = *(const float4*)(Vmat + base + (long)(n + r) * DIM_ + c4);
        }
        __syncthreads();
#pragma unroll
        for (int kk = 0; kk < CH; kk++) {
            float kr[4], vr[4];
#pragma unroll
            for (int i = 0; i < 4; i++) kr[i] = Ks[kk][ty * 4 + i];
#pragma unroll
            for (int j = 0; j < 4; j++) vr[j] = Vs[kk][tx * 4 + j];
#pragma unroll
            for (int i = 0; i < 4; i++)
#pragma unroll
                for (int j = 0; j < 4; j++)
                    acc[i][j] = fmaf(kr[i], vr[j], acc[i][j]);
        }
        __syncthreads();
    }

    float* out = Gp + ((long)split * BSZ * HEADS + bh) * HD * HD;
#pragma unroll
    for (int i = 0; i < 4; i++)
#pragma unroll
        for (int j = 0; j < 4; j++)
            out[(ty * 4 + i) * HD + tx * 4 + j] = acc[i][j];
}

// ---------------- reduce G partials, M = P @ G ------------------------------
__global__ __launch_bounds__(256) void gm_kernel(const float* __restrict__ Gp,
                                                 const float* __restrict__ P,
                                                 float* __restrict__ Mout)
{
    const int bh = blockIdx.x;
    __shared__ float Gs[HD][HD];
    __shared__ float Ps[HD][HD];
    const int tid = threadIdx.x;

    for (int t = tid; t < HD * HD; t += 256) {
        float s = 0.f;
#pragma unroll
        for (int sp = 0; sp < GSPLIT; sp++)
            s += Gp[((long)sp * BSZ * HEADS + bh) * HD * HD + t];
        Gs[t / HD][t % HD] = s;
        Ps[t / HD][t % HD] = P[t];
    }
    __syncthreads();

    const int e = tid / 4;
    const int d0 = (tid % 4) * 16;
    float acc[16];
#pragma unroll
    for (int j = 0; j < 16; j++) acc[j] = 0.f;
#pragma unroll 8
    for (int c = 0; c < HD; c++) {
        float pe = Ps[e][c];
#pragma unroll
        for (int j = 0; j < 16; j++)
            acc[j] = fmaf(pe, Gs[c][d0 + j], acc[j]);
    }
#pragma unroll
    for (int j = 0; j < 16; j++)
        Mout[(long)bh * HD * HD + e * HD + d0 + j] = acc[j];
}

// ---------------- W2t(b)[c, h*64+e] = sum_d M(b,h)[e,d] * Wo[h*64+d, c] -----
__global__ __launch_bounds__(256) void w2_kernel(const float* __restrict__ Mmat,
                                                 const float* __restrict__ Wo,
                                                 __half* __restrict__ W2t)
{
    const int bh = blockIdx.x;
    const int b = bh / HEADS, h = bh % HEADS;
    const int c0 = blockIdx.y * 128;

    __shared__ float Ms[HD][HD];
    const int tid = threadIdx.x;
    for (int t = tid; t < HD * HD; t += 256)
        Ms[t / HD][t % HD] = Mmat[(long)bh * HD * HD + t];
    __syncthreads();

    const int col = c0 + (tid & 127);
    const int e0  = (tid >> 7) * 32;
    float acc[32];
#pragma unroll
    for (int e = 0; e < 32; e++) acc[e] = 0.f;
#pragma unroll 4
    for (int d = 0; d < HD; d++) {
        float w = Wo[(long)(h * HD + d) * DIM_ + col];
#pragma unroll
        for (int e = 0; e < 32; e++)
            acc[e] = fmaf(Ms[e0 + e][d], w, acc[e]);
    }
    const long obase = (long)b * DIM_ * DIM_ + (long)col * DIM_ + h * HD + e0;
#pragma unroll
    for (int e = 0; e < 32; e++)
        W2t[obase + e] = __float2half_rn(acc[e]);
}

// ---------------- launch ----------------------------------------------------
extern "C" void kernel_launch(void* const* d_in, const int* in_sizes, int n_in,
                              void* d_out, int out_size)
{
    const float* x   = (const float*)d_in[0];
    const float* Wq  = (const float*)d_in[1];
    const float* bq  = (const float*)d_in[2];
    const float* Wk  = (const float*)d_in[3];
    const float* bk  = (const float*)d_in[4];
    const float* Wv  = (const float*)d_in[5];
    const float* bv  = (const float*)d_in[6];
    const float* Wo  = (const float*)d_in[7];
    const float* bo  = (const float*)d_in[8];
    const float* RF  = (const float*)d_in[9];
    float* out = (float*)d_out;

    __half *x16, *q116, *wt16, *w2t16;
    float *kp, *vp, *gpp, *pp, *mp;
    cudaGetSymbolAddress((void**)&x16,   g_x16);
    cudaGetSymbolAddress((void**)&q116,  g_q116);
    cudaGetSymbolAddress((void**)&kp,    g_k);
    cudaGetSymbolAddress((void**)&vp,    g_v);
    cudaGetSymbolAddress((void**)&wt16,  g_wt16);
    cudaGetSymbolAddress((void**)&w2t16, g_w2t16);
    cudaGetSymbolAddress((void**)&gpp,   g_Gpart);
    cudaGetSymbolAddress((void**)&pp,    g_P);
    cudaGetSymbolAddress((void**)&mp,    g_M);

    cudaFuncSetAttribute(gemm_tc<1, 1>, cudaFuncAttributeMaxDynamicSharedMemorySize, GEMM_SMEM);
    cudaFuncSetAttribute(gemm_tc<1, 0>, cudaFuncAttributeMaxDynamicSharedMemorySize, GEMM_SMEM);
    cudaFuncSetAttribute(gemm_tc<0, 0>, cudaFuncAttributeMaxDynamicSharedMemorySize, GEMM_SMEM);

    const size_t WSZ = (size_t)DIM_ * DIM_;

    // 1) x -> fp16 (shared A for all 3 projections)
    conv_x_kernel<<<(ROWS * DIM_ / 4 + 255) / 256, 256>>>(
        (const float4*)x, (uint2*)x16, ROWS * DIM_ / 4);

    // 2) transpose weights -> fp16
    dim3 wgrid(32, 32), wblk(32, 32);
    conv_w_kernel<<<wgrid, wblk>>>(Wq, wt16 + 0 * WSZ);
    conv_w_kernel<<<wgrid, wblk>>>(Wk, wt16 + 1 * WSZ);
    conv_w_kernel<<<wgrid, wblk>>>(Wv, wt16 + 2 * WSZ);

    // 3) QKV projections on tensor cores (fp16 mma.sync)
    dim3 gq(DIM_ / 128, ROWS / 128, 1);
    gemm_tc<1, 1><<<gq, 256, GEMM_SMEM>>>(x16, wt16 + 0 * WSZ, bq,
                                          nullptr, q116, DIM_, DIM_, 0, 0, 0);
    gemm_tc<1, 0><<<gq, 256, GEMM_SMEM>>>(x16, wt16 + 1 * WSZ, bk,
                                          kp, nullptr, DIM_, DIM_, 0, 0, 0);
    gemm_tc<0, 0><<<gq, 256, GEMM_SMEM>>>(x16, wt16 + 2 * WSZ, bv,
                                          vp, nullptr, DIM_, DIM_, 0, 0, 0);

    // 4) P = RF @ RF^T
    pmat_kernel<<<1, 256>>>(RF, pp);

    // 5) G partials: k1^T v per (b,h)
    kv_outer_kernel<<<dim3(BSZ * HEADS, GSPLIT), 256>>>(kp, vp, gpp);

    // 6) reduce + M = P @ G
    gm_kernel<<<BSZ * HEADS, 256>>>(gpp, pp, mp);

    // 7) W2t(b) = (blockdiag(M) @ Wo)^T, fp16
    w2_kernel<<<dim3(BSZ * HEADS, DIM_ / 128), 256>>>(mp, Wo, w2t16);

    // 8) final: out(b) = q1(b) @ W2(b) + bo (batched, tensor cores)
    dim3 gf(DIM_ / 128, NLEN / 128, BSZ);
    gemm_tc<0, 0><<<gf, 256, GEMM_SMEM>>>(q116, w2t16, bo,
                                          out, nullptr, DIM_, DIM_,
                                          (long)NLEN * DIM_, (long)DIM_ * DIM_,
                                          (long)NLEN * DIM_);
}